// round 4
// baseline (speedup 1.0000x reference)
#include <cuda_runtime.h>
#include <cuda_bf16.h>
#include <cstdint>

// TinyMoE: N=8192 tokens, H=1024, E=8, top-2.
// out[n,h] = sum_k w_k * (x[n] @ W_{e_k})[h] + C_n
//
// R4: HMMA bf16 expert GEMM with de-duplicated 3-term split.
// Per 64-k slab load 4 tiles (Axh, Axl, Bwh, Bwl) once; issue 3 MMA terms
// hh + hl + lh into one fp32 accumulator. 1 CTA/SM, 192KB smem, 3-stage
// cp.async pipeline.

#define H      1024
#define NTOK   8192
#define NEXP   8
#define MAXPE  16384
#define BM     128
#define BN     128
#define BKH    64            // bf16 per k-slab (128 bytes)
#define KITER  (H / BKH)     // 16
#define PSTAGE 3

__device__ int   g_count[NEXP];
__device__ int   g_tok [NEXP][MAXPE];
__device__ float g_wt  [NEXP][MAXPE];
__device__ int   g_slot[NEXP][MAXPE];
__device__ float g_C   [NTOK];
__device__ float g_buf [2][(size_t)NTOK * H];
__device__ __nv_bfloat16 g_xh[(size_t)NTOK * H];
__device__ __nv_bfloat16 g_xl[(size_t)NTOK * H];
__device__ __nv_bfloat16 g_wh[(size_t)NEXP * H * H];   // [e][out][in]
__device__ __nv_bfloat16 g_wl[(size_t)NEXP * H * H];

// ------------------------------------------------------------------ utils
__device__ __forceinline__ uint32_t smem_u32(const void* p) {
    uint32_t a;
    asm("{ .reg .u64 t; cvta.to.shared.u64 t, %1; cvt.u32.u64 %0, t; }"
        : "=r"(a) : "l"(p));
    return a;
}
#define SWZ(o) ((o) ^ ((((uint32_t)(o)) >> 3) & 0x70))

__device__ __forceinline__ void cp16(uint32_t d, const void* s) {
    asm volatile("cp.async.cg.shared.global [%0], [%1], 16;" :: "r"(d), "l"(s));
}
#define CP_COMMIT()  asm volatile("cp.async.commit_group;" ::: "memory")
#define CP_WAIT1()   asm volatile("cp.async.wait_group 1;" ::: "memory")

__device__ __forceinline__ void ldm4(uint32_t a, uint32_t& r0, uint32_t& r1,
                                     uint32_t& r2, uint32_t& r3) {
    asm volatile("ldmatrix.sync.aligned.m8n8.x4.shared.b16 {%0,%1,%2,%3}, [%4];"
                 : "=r"(r0), "=r"(r1), "=r"(r2), "=r"(r3) : "r"(a));
}
__device__ __forceinline__ void mma16816(float* c, const uint32_t* a,
                                         uint32_t b0, uint32_t b1) {
    asm volatile(
        "mma.sync.aligned.m16n8k16.row.col.f32.bf16.bf16.f32 "
        "{%0,%1,%2,%3}, {%4,%5,%6,%7}, {%8,%9}, {%0,%1,%2,%3};"
        : "+f"(c[0]), "+f"(c[1]), "+f"(c[2]), "+f"(c[3])
        : "r"(a[0]), "r"(a[1]), "r"(a[2]), "r"(a[3]), "r"(b0), "r"(b1));
}

// ------------------------------------------------------------------ stage 0
__global__ void reset_kernel() {
    if (threadIdx.x < NEXP) g_count[threadIdx.x] = 0;
}

// ------------------------------------------------------------------ convert x
__global__ __launch_bounds__(256) void convert_x(const float* __restrict__ x) {
    size_t i = ((size_t)blockIdx.x * 256 + threadIdx.x) * 4;
    float4 v = *(const float4*)(x + i);
    __nv_bfloat16 h0 = __float2bfloat16(v.x), h1 = __float2bfloat16(v.y);
    __nv_bfloat16 h2 = __float2bfloat16(v.z), h3 = __float2bfloat16(v.w);
    __nv_bfloat16 l0 = __float2bfloat16(v.x - __bfloat162float(h0));
    __nv_bfloat16 l1 = __float2bfloat16(v.y - __bfloat162float(h1));
    __nv_bfloat16 l2 = __float2bfloat16(v.z - __bfloat162float(h2));
    __nv_bfloat16 l3 = __float2bfloat16(v.w - __bfloat162float(h3));
    __nv_bfloat162* ph = (__nv_bfloat162*)(g_xh + i);
    __nv_bfloat162* pl = (__nv_bfloat162*)(g_xl + i);
    ph[0] = __halves2bfloat162(h0, h1); ph[1] = __halves2bfloat162(h2, h3);
    pl[0] = __halves2bfloat162(l0, l1); pl[1] = __halves2bfloat162(l2, l3);
}

// ------------------------------------------------------------------ convert+transpose W
// W[e][in][out] fp32 -> g_wh/g_wl[e][out][in] bf16
__global__ __launch_bounds__(256) void convert_w(const float* __restrict__ W) {
    __shared__ float tile[32][33];
    int e = blockIdx.z, h0 = blockIdx.x * 32, o0 = blockIdx.y * 32;
    int tx = threadIdx.x & 31, ty = threadIdx.x >> 5;
    const float* src = W + ((size_t)e * H + h0) * H + o0;
    #pragma unroll
    for (int r = ty; r < 32; r += 8)
        tile[r][tx] = src[(size_t)r * H + tx];
    __syncthreads();
    #pragma unroll
    for (int r = ty; r < 32; r += 8) {
        float v = tile[tx][r];   // W[h0+tx][o0+r]
        __nv_bfloat16 hi = __float2bfloat16(v);
        __nv_bfloat16 lo = __float2bfloat16(v - __bfloat162float(hi));
        size_t o = ((size_t)e * H + o0 + r) * H + h0 + tx;
        g_wh[o] = hi;
        g_wl[o] = lo;
    }
}

// ------------------------------------------------------------------ router
__global__ __launch_bounds__(256) void router_kernel(const float* __restrict__ x,
                                                     const float* __restrict__ rw) {
    __shared__ float s_rw[NEXP * H];
    int t = threadIdx.x;
    {
        const float4* rw4 = (const float4*)rw;
        float4* s4 = (float4*)s_rw;
        #pragma unroll
        for (int i = 0; i < (NEXP * H / 4) / 256; i++)
            s4[t + i * 256] = rw4[t + i * 256];
    }
    __syncthreads();

    int wid = t >> 5, lane = t & 31;
    int n = blockIdx.x * 8 + wid;
    const float4* xr = (const float4*)(x + (size_t)n * H);
    const float4* rw4 = (const float4*)s_rw;

    float acc[NEXP];
    #pragma unroll
    for (int e = 0; e < NEXP; e++) acc[e] = 0.f;
    #pragma unroll
    for (int i = 0; i < 8; i++) {                 // 8 x float4 per lane
        float4 xv = xr[i * 32 + lane];
        #pragma unroll
        for (int e = 0; e < NEXP; e++) {
            float4 rv = rw4[e * 256 + i * 32 + lane];
            acc[e] += xv.x * rv.x + xv.y * rv.y + xv.z * rv.z + xv.w * rv.w;
        }
    }
    #pragma unroll
    for (int e = 0; e < NEXP; e++) {
        #pragma unroll
        for (int off = 16; off > 0; off >>= 1)
            acc[e] += __shfl_xor_sync(0xffffffffu, acc[e], off);
    }
    if (lane == 0) {
        float m = acc[0];
        #pragma unroll
        for (int e = 1; e < NEXP; e++) m = fmaxf(m, acc[e]);
        float p[NEXP]; float s = 0.f;
        #pragma unroll
        for (int e = 0; e < NEXP; e++) { p[e] = expf(acc[e] - m); s += p[e]; }
        float inv = 1.f / s;
        int b1 = 0; float v1 = acc[0];
        #pragma unroll
        for (int e = 1; e < NEXP; e++) if (acc[e] > v1) { v1 = acc[e]; b1 = e; }
        int b2 = -1; float v2 = -3.4e38f;
        #pragma unroll
        for (int e = 0; e < NEXP; e++)
            if (e != b1 && acc[e] > v2) { v2 = acc[e]; b2 = e; }
        float p0 = p[b1] * inv, p1 = p[b2] * inv;
        float ws = 1.f / (p0 + p1 + 1e-6f);
        float w0 = p0 * ws, w1 = p1 * ws;
        g_C[n] = w0 * p0 + w1 * p1;
        int pos0 = atomicAdd(&g_count[b1], 1);
        g_tok[b1][pos0] = n; g_wt[b1][pos0] = w0; g_slot[b1][pos0] = 0;
        int pos1 = atomicAdd(&g_count[b2], 1);
        g_tok[b2][pos1] = n; g_wt[b2][pos1] = w1; g_slot[b2][pos1] = 1;
    }
}

// ------------------------------------------------------------------ HMMA GEMM
// 128x128 tile, physical K=1024, 4 tiles per k-slab (Axh,Axl,Bwh,Bwl),
// 3 MMA terms per slab. 3-stage cp.async pipeline, 8 warps (2x4), warp 64x32.
#define TILE_B      16384
#define STAGE_BYTES (4 * TILE_B)                // 64 KB
#define SMEM_BYTES  (PSTAGE * STAGE_BYTES)      // 192 KB

__global__ __launch_bounds__(256, 1) void expert_gemm() {
    extern __shared__ char smem[];
    __shared__ int   s_tok[BM];
    __shared__ float s_wt [BM];
    __shared__ int   s_slot[BM];

    int e = blockIdx.z;
    int cnt = g_count[e];
    int m0 = blockIdx.x * BM;
    if (m0 >= cnt) return;
    int n0 = blockIdx.y * BN;

    int t = threadIdx.x;
    if (t < BM) {
        int src = min(m0 + t, cnt - 1);
        s_tok[t]  = g_tok[e][src];
        s_wt[t]   = g_wt[e][src];
        s_slot[t] = g_slot[e][src];
    }
    __syncthreads();

    const uint32_t sb = smem_u32(smem);

    // ---- loader: thread t covers rows lr+32*i (i<4), 16B chunk lc
    const int lr = t >> 3, lc = t & 7;
    const __nv_bfloat16* axh[4];
    const __nv_bfloat16* axl[4];
    const __nv_bfloat16* bwh[4];
    const __nv_bfloat16* bwl[4];
    #pragma unroll
    for (int i = 0; i < 4; i++) {
        int r = lr + 32 * i;
        size_t xoff = (size_t)s_tok[r] * H + lc * 8;
        size_t woff = ((size_t)e * H + n0 + r) * H + lc * 8;
        axh[i] = g_xh + xoff;
        axl[i] = g_xl + xoff;
        bwh[i] = g_wh + woff;
        bwl[i] = g_wl + woff;
    }
    const uint32_t dsw = SWZ(lr * 128 + lc * 16);

    #define ISSUE(it) do {                                                   \
        int _st = (it) % PSTAGE; int _k0 = (it) * BKH;                       \
        uint32_t _s0 = sb + _st * STAGE_BYTES;                               \
        _Pragma("unroll")                                                    \
        for (int _i = 0; _i < 4; _i++) {                                     \
            uint32_t _d = dsw + _i * 4096;                                   \
            cp16(_s0 +              _d, axh[_i] + _k0);                      \
            cp16(_s0 +     TILE_B + _d, axl[_i] + _k0);                      \
            cp16(_s0 + 2 * TILE_B + _d, bwh[_i] + _k0);                      \
            cp16(_s0 + 3 * TILE_B + _d, bwl[_i] + _k0);                      \
        }                                                                    \
    } while (0)

    ISSUE(0); CP_COMMIT();
    ISSUE(1); CP_COMMIT();

    // ---- compute setup: 8 warps as 2(M) x 4(N), warp tile 64x32
    int lane = t & 31, wid = t >> 5;
    int wm = wid & 1, wn = wid >> 1;
    int arow0 = wm * 64 + (lane & 15);
    int brow0 = wn * 32 + (lane & 15);
    int csel  = (lane >> 4) * 16;

    float acc[4][4][4];
    #pragma unroll
    for (int a = 0; a < 4; a++)
        #pragma unroll
        for (int b = 0; b < 4; b++)
            #pragma unroll
            for (int c = 0; c < 4; c++) acc[a][b][c] = 0.f;

    for (int it = 0; it < KITER; it++) {
        CP_WAIT1();
        __syncthreads();
        if (it + 2 < KITER) { ISSUE(it + 2); }
        CP_COMMIT();

        uint32_t s0  = sb + (it % PSTAGE) * STAGE_BYTES;
        uint32_t ahb = s0;
        uint32_t alb = s0 + TILE_B;
        uint32_t bhb = s0 + 2 * TILE_B;
        uint32_t blb = s0 + 3 * TILE_B;
        #pragma unroll
        for (int kk = 0; kk < 4; kk++) {
            int colb = kk * 32 + csel;
            uint32_t afh[4][4], afl[4][4];
            #pragma unroll
            for (int im = 0; im < 4; im++) {
                uint32_t ro = SWZ((arow0 + im * 16) * 128 + colb);
                ldm4(ahb + ro, afh[im][0], afh[im][1], afh[im][2], afh[im][3]);
                ldm4(alb + ro, afl[im][0], afl[im][1], afl[im][2], afl[im][3]);
            }
            uint32_t bfh[2][4], bfl[2][4];
            #pragma unroll
            for (int j = 0; j < 2; j++) {
                uint32_t ro = SWZ((brow0 + j * 16) * 128 + colb);
                ldm4(bhb + ro, bfh[j][0], bfh[j][1], bfh[j][2], bfh[j][3]);
                ldm4(blb + ro, bfl[j][0], bfl[j][1], bfl[j][2], bfl[j][3]);
            }
            #pragma unroll
            for (int im = 0; im < 4; im++) {
                // term hh
                mma16816(acc[im][0], afh[im], bfh[0][0], bfh[0][2]);
                mma16816(acc[im][1], afh[im], bfh[0][1], bfh[0][3]);
                mma16816(acc[im][2], afh[im], bfh[1][0], bfh[1][2]);
                mma16816(acc[im][3], afh[im], bfh[1][1], bfh[1][3]);
                // term hl
                mma16816(acc[im][0], afh[im], bfl[0][0], bfl[0][2]);
                mma16816(acc[im][1], afh[im], bfl[0][1], bfl[0][3]);
                mma16816(acc[im][2], afh[im], bfl[1][0], bfl[1][2]);
                mma16816(acc[im][3], afh[im], bfl[1][1], bfl[1][3]);
                // term lh
                mma16816(acc[im][0], afl[im], bfh[0][0], bfh[0][2]);
                mma16816(acc[im][1], afl[im], bfh[0][1], bfh[0][3]);
                mma16816(acc[im][2], afl[im], bfh[1][0], bfh[1][2]);
                mma16816(acc[im][3], afl[im], bfh[1][1], bfh[1][3]);
            }
        }
        __syncthreads();
    }

    // ---- epilogue: scale by routing weight, scatter rows
    int qr = lane >> 2, qc = (lane & 3) * 2;
    #pragma unroll
    for (int im = 0; im < 4; im++) {
        #pragma unroll
        for (int p = 0; p < 2; p++) {
            int r = wm * 64 + im * 16 + p * 8 + qr;
            if (m0 + r < cnt) {
                float wt = s_wt[r];
                float* dst = g_buf[s_slot[r]] + (size_t)s_tok[r] * H + n0 + wn * 32 + qc;
                #pragma unroll
                for (int inn = 0; inn < 4; inn++) {
                    float2 v;
                    v.x = acc[im][inn][p * 2 + 0] * wt;
                    v.y = acc[im][inn][p * 2 + 1] * wt;
                    *(float2*)(dst + inn * 8) = v;
                }
            }
        }
    }
}

// ------------------------------------------------------------------ combine
__global__ __launch_bounds__(256) void combine_kernel(float* __restrict__ out) {
    size_t idx = (size_t)blockIdx.x * 256 + threadIdx.x;  // float4 index
    int n = (int)(idx >> 8);
    float4 a = ((const float4*)g_buf[0])[idx];
    float4 b = ((const float4*)g_buf[1])[idx];
    float  c = g_C[n];
    float4 o;
    o.x = a.x + b.x + c;
    o.y = a.y + b.y + c;
    o.z = a.z + b.z + c;
    o.w = a.w + b.w + c;
    ((float4*)out)[idx] = o;
}

// ------------------------------------------------------------------ launch
extern "C" void kernel_launch(void* const* d_in, const int* in_sizes, int n_in,
                              void* d_out, int out_size) {
    const float* x  = (const float*)d_in[0];   // [8192, 1024]
    const float* rw = (const float*)d_in[1];   // [8, 1024]
    const float* W  = (const float*)d_in[2];   // [8, 1024, 1024]
    float* out = (float*)d_out;

    cudaFuncSetAttribute(expert_gemm, cudaFuncAttributeMaxDynamicSharedMemorySize,
                         SMEM_BYTES);

    reset_kernel<<<1, 32>>>();
    convert_x<<<(NTOK * H / 4) / 256, 256>>>(x);
    convert_w<<<dim3(H / 32, H / 32, NEXP), 256>>>(W);
    router_kernel<<<NTOK / 8, 256>>>(x, rw);
    expert_gemm<<<dim3(MAXPE / BM, H / BN, NEXP), 256, SMEM_BYTES>>>();
    combine_kernel<<<(NTOK * H / 4) / 256, 256>>>(out);
}

// round 5
// speedup vs baseline: 1.9723x; 1.9723x over previous
#include <cuda_runtime.h>
#include <cuda_fp16.h>
#include <cstdint>

// TinyMoE: N=8192 tokens, H=1024, E=8, top-2.
// out[n,h] = sum_k w_k * (x[n] @ W_{e_k})[h] + C_n
//
// R5: single-term fp16 HMMA expert GEMM (fp32 accumulate). fp16 quantization
// gives ~1e-4 L2 rel err (budget 1e-3), so the 3-term bf16 split is dropped:
// 3x fewer MMAs, 2x less operand traffic. Pipeline = R3's proven occ-2
// 3-stage cp.async structure (32KB/stage, 96KB total).

#define H      1024
#define NTOK   8192
#define NEXP   8
#define MAXPE  16384
#define BM     128
#define BN     128
#define BKH    64            // fp16 per k-slab (128 bytes)
#define KITER  (H / BKH)     // 16
#define PSTAGE 3

__device__ int    g_count[NEXP];
__device__ int    g_tok [NEXP][MAXPE];
__device__ float  g_wt  [NEXP][MAXPE];
__device__ int    g_slot[NEXP][MAXPE];
__device__ float  g_C   [NTOK];
__device__ float  g_buf [2][(size_t)NTOK * H];
__device__ __half g_xh[(size_t)NTOK * H];
__device__ __half g_wh[(size_t)NEXP * H * H];   // [e][out][in]

// ------------------------------------------------------------------ utils
__device__ __forceinline__ uint32_t smem_u32(const void* p) {
    uint32_t a;
    asm("{ .reg .u64 t; cvta.to.shared.u64 t, %1; cvt.u32.u64 %0, t; }"
        : "=r"(a) : "l"(p));
    return a;
}
#define SWZ(o) ((o) ^ ((((uint32_t)(o)) >> 3) & 0x70))

__device__ __forceinline__ void cp16(uint32_t d, const void* s) {
    asm volatile("cp.async.cg.shared.global [%0], [%1], 16;" :: "r"(d), "l"(s));
}
#define CP_COMMIT()  asm volatile("cp.async.commit_group;" ::: "memory")
#define CP_WAIT1()   asm volatile("cp.async.wait_group 1;" ::: "memory")

__device__ __forceinline__ void ldm4(uint32_t a, uint32_t& r0, uint32_t& r1,
                                     uint32_t& r2, uint32_t& r3) {
    asm volatile("ldmatrix.sync.aligned.m8n8.x4.shared.b16 {%0,%1,%2,%3}, [%4];"
                 : "=r"(r0), "=r"(r1), "=r"(r2), "=r"(r3) : "r"(a));
}
__device__ __forceinline__ void mma16816(float* c, const uint32_t* a,
                                         uint32_t b0, uint32_t b1) {
    asm volatile(
        "mma.sync.aligned.m16n8k16.row.col.f32.f16.f16.f32 "
        "{%0,%1,%2,%3}, {%4,%5,%6,%7}, {%8,%9}, {%0,%1,%2,%3};"
        : "+f"(c[0]), "+f"(c[1]), "+f"(c[2]), "+f"(c[3])
        : "r"(a[0]), "r"(a[1]), "r"(a[2]), "r"(a[3]), "r"(b0), "r"(b1));
}

// ------------------------------------------------------------------ stage 0
__global__ void reset_kernel() {
    if (threadIdx.x < NEXP) g_count[threadIdx.x] = 0;
}

// ------------------------------------------------------------------ convert x
__global__ __launch_bounds__(256) void convert_x(const float* __restrict__ x) {
    size_t i = ((size_t)blockIdx.x * 256 + threadIdx.x) * 4;
    float4 v = *(const float4*)(x + i);
    __half2* ph = (__half2*)(g_xh + i);
    ph[0] = __floats2half2_rn(v.x, v.y);
    ph[1] = __floats2half2_rn(v.z, v.w);
}

// ------------------------------------------------------------------ convert+transpose W
// W[e][in][out] fp32 -> g_wh[e][out][in] fp16
__global__ __launch_bounds__(256) void convert_w(const float* __restrict__ W) {
    __shared__ float tile[32][33];
    int e = blockIdx.z, h0 = blockIdx.x * 32, o0 = blockIdx.y * 32;
    int tx = threadIdx.x & 31, ty = threadIdx.x >> 5;
    const float* src = W + ((size_t)e * H + h0) * H + o0;
    #pragma unroll
    for (int r = ty; r < 32; r += 8)
        tile[r][tx] = src[(size_t)r * H + tx];
    __syncthreads();
    #pragma unroll
    for (int r = ty; r < 32; r += 8) {
        float v = tile[tx][r];   // W[h0+tx][o0+r]
        g_wh[((size_t)e * H + o0 + r) * H + h0 + tx] = __float2half_rn(v);
    }
}

// ------------------------------------------------------------------ router
// 128 blocks; each warp handles 8 tokens; rw cached once per block.
__global__ __launch_bounds__(256) void router_kernel(const float* __restrict__ x,
                                                     const float* __restrict__ rw) {
    __shared__ float s_rw[NEXP * H];
    int t = threadIdx.x;
    {
        const float4* rwg = (const float4*)rw;
        float4* s4 = (float4*)s_rw;
        #pragma unroll
        for (int i = 0; i < (NEXP * H / 4) / 256; i++)
            s4[t + i * 256] = rwg[t + i * 256];
    }
    __syncthreads();

    int wid = t >> 5, lane = t & 31;
    const float4* rw4 = (const float4*)s_rw;

    for (int j = 0; j < 8; j++) {
        int n = blockIdx.x * 64 + wid * 8 + j;
        const float4* xr = (const float4*)(x + (size_t)n * H);

        float acc[NEXP];
        #pragma unroll
        for (int e = 0; e < NEXP; e++) acc[e] = 0.f;
        #pragma unroll
        for (int i = 0; i < 8; i++) {
            float4 xv = xr[i * 32 + lane];
            #pragma unroll
            for (int e = 0; e < NEXP; e++) {
                float4 rv = rw4[e * 256 + i * 32 + lane];
                acc[e] += xv.x * rv.x + xv.y * rv.y + xv.z * rv.z + xv.w * rv.w;
            }
        }
        #pragma unroll
        for (int e = 0; e < NEXP; e++) {
            #pragma unroll
            for (int off = 16; off > 0; off >>= 1)
                acc[e] += __shfl_xor_sync(0xffffffffu, acc[e], off);
        }
        if (lane == 0) {
            float m = acc[0];
            #pragma unroll
            for (int e = 1; e < NEXP; e++) m = fmaxf(m, acc[e]);
            float p[NEXP]; float s = 0.f;
            #pragma unroll
            for (int e = 0; e < NEXP; e++) { p[e] = expf(acc[e] - m); s += p[e]; }
            float inv = 1.f / s;
            int b1 = 0; float v1 = acc[0];
            #pragma unroll
            for (int e = 1; e < NEXP; e++) if (acc[e] > v1) { v1 = acc[e]; b1 = e; }
            int b2 = -1; float v2 = -3.4e38f;
            #pragma unroll
            for (int e = 0; e < NEXP; e++)
                if (e != b1 && acc[e] > v2) { v2 = acc[e]; b2 = e; }
            float p0 = p[b1] * inv, p1 = p[b2] * inv;
            float ws = 1.f / (p0 + p1 + 1e-6f);
            float w0 = p0 * ws, w1 = p1 * ws;
            g_C[n] = w0 * p0 + w1 * p1;
            int pos0 = atomicAdd(&g_count[b1], 1);
            g_tok[b1][pos0] = n; g_wt[b1][pos0] = w0; g_slot[b1][pos0] = 0;
            int pos1 = atomicAdd(&g_count[b2], 1);
            g_tok[b2][pos1] = n; g_wt[b2][pos1] = w1; g_slot[b2][pos1] = 1;
        }
    }
}

// ------------------------------------------------------------------ HMMA GEMM
// 128x128 tile, K=1024, 3-stage cp.async pipeline, 8 warps (2x4), warp 64x32.
#define STAGE_BYTES 32768                       // A 16KB + B 16KB
#define SMEM_BYTES  (PSTAGE * STAGE_BYTES)      // 96 KB -> 2 CTAs/SM

__global__ __launch_bounds__(256, 2) void expert_gemm() {
    extern __shared__ char smem[];
    __shared__ int   s_tok[BM];
    __shared__ float s_wt [BM];
    __shared__ int   s_slot[BM];

    int e = blockIdx.z;
    int cnt = g_count[e];
    int m0 = blockIdx.x * BM;
    if (m0 >= cnt) return;
    int n0 = blockIdx.y * BN;

    int t = threadIdx.x;
    if (t < BM) {
        int src = min(m0 + t, cnt - 1);
        s_tok[t]  = g_tok[e][src];
        s_wt[t]   = g_wt[e][src];
        s_slot[t] = g_slot[e][src];
    }
    __syncthreads();

    const uint32_t sb = smem_u32(smem);

    // ---- loader: thread t covers rows lr+32*i (i<4), 16B chunk lc
    const int lr = t >> 3, lc = t & 7;
    const __half* aptr[4];
    const __half* bptr[4];
    #pragma unroll
    for (int i = 0; i < 4; i++) {
        int r = lr + 32 * i;
        aptr[i] = g_xh + (size_t)s_tok[r] * H + lc * 8;
        bptr[i] = g_wh + ((size_t)e * H + n0 + r) * H + lc * 8;
    }
    const uint32_t dsw = SWZ(lr * 128 + lc * 16);

    #define ISSUE(it) do {                                                   \
        int _st = (it) % PSTAGE; int _k0 = (it) * BKH;                       \
        uint32_t _ab = sb + _st * STAGE_BYTES;                               \
        uint32_t _bb = _ab + 16384;                                          \
        _Pragma("unroll")                                                    \
        for (int _i = 0; _i < 4; _i++) {                                     \
            cp16(_ab + (dsw + _i * 4096), aptr[_i] + _k0);                   \
            cp16(_bb + (dsw + _i * 4096), bptr[_i] + _k0);                   \
        }                                                                    \
    } while (0)

    ISSUE(0); CP_COMMIT();
    ISSUE(1); CP_COMMIT();

    // ---- compute setup: 8 warps as 2(M) x 4(N), warp tile 64x32
    int lane = t & 31, wid = t >> 5;
    int wm = wid & 1, wn = wid >> 1;
    int arow0 = wm * 64 + (lane & 15);
    int brow0 = wn * 32 + (lane & 15);
    int csel  = (lane >> 4) * 16;

    float acc[4][4][4];
    #pragma unroll
    for (int a = 0; a < 4; a++)
        #pragma unroll
        for (int b = 0; b < 4; b++)
            #pragma unroll
            for (int c = 0; c < 4; c++) acc[a][b][c] = 0.f;

    for (int it = 0; it < KITER; it++) {
        CP_WAIT1();
        __syncthreads();
        if (it + 2 < KITER) { ISSUE(it + 2); }
        CP_COMMIT();

        uint32_t ab = sb + (it % PSTAGE) * STAGE_BYTES;
        uint32_t bb = ab + 16384;
        #pragma unroll
        for (int kk = 0; kk < 4; kk++) {
            int colb = kk * 32 + csel;
            uint32_t afr[4][4];
            #pragma unroll
            for (int im = 0; im < 4; im++)
                ldm4(ab + SWZ((arow0 + im * 16) * 128 + colb),
                     afr[im][0], afr[im][1], afr[im][2], afr[im][3]);
            uint32_t bfr[2][4];
            #pragma unroll
            for (int j = 0; j < 2; j++)
                ldm4(bb + SWZ((brow0 + j * 16) * 128 + colb),
                     bfr[j][0], bfr[j][1], bfr[j][2], bfr[j][3]);
            #pragma unroll
            for (int im = 0; im < 4; im++) {
                mma16816(acc[im][0], afr[im], bfr[0][0], bfr[0][2]);
                mma16816(acc[im][1], afr[im], bfr[0][1], bfr[0][3]);
                mma16816(acc[im][2], afr[im], bfr[1][0], bfr[1][2]);
                mma16816(acc[im][3], afr[im], bfr[1][1], bfr[1][3]);
            }
        }
        __syncthreads();
    }

    // ---- epilogue: scale by routing weight, scatter rows
    int qr = lane >> 2, qc = (lane & 3) * 2;
    #pragma unroll
    for (int im = 0; im < 4; im++) {
        #pragma unroll
        for (int p = 0; p < 2; p++) {
            int r = wm * 64 + im * 16 + p * 8 + qr;
            if (m0 + r < cnt) {
                float wt = s_wt[r];
                float* dst = g_buf[s_slot[r]] + (size_t)s_tok[r] * H + n0 + wn * 32 + qc;
                #pragma unroll
                for (int inn = 0; inn < 4; inn++) {
                    float2 v;
                    v.x = acc[im][inn][p * 2 + 0] * wt;
                    v.y = acc[im][inn][p * 2 + 1] * wt;
                    *(float2*)(dst + inn * 8) = v;
                }
            }
        }
    }
}

// ------------------------------------------------------------------ combine
__global__ __launch_bounds__(256) void combine_kernel(float* __restrict__ out) {
    size_t idx = (size_t)blockIdx.x * 256 + threadIdx.x;  // float4 index
    int n = (int)(idx >> 8);
    float4 a = ((const float4*)g_buf[0])[idx];
    float4 b = ((const float4*)g_buf[1])[idx];
    float  c = g_C[n];
    float4 o;
    o.x = a.x + b.x + c;
    o.y = a.y + b.y + c;
    o.z = a.z + b.z + c;
    o.w = a.w + b.w + c;
    ((float4*)out)[idx] = o;
}

// ------------------------------------------------------------------ launch
extern "C" void kernel_launch(void* const* d_in, const int* in_sizes, int n_in,
                              void* d_out, int out_size) {
    const float* x  = (const float*)d_in[0];   // [8192, 1024]
    const float* rw = (const float*)d_in[1];   // [8, 1024]
    const float* W  = (const float*)d_in[2];   // [8, 1024, 1024]
    float* out = (float*)d_out;

    cudaFuncSetAttribute(expert_gemm, cudaFuncAttributeMaxDynamicSharedMemorySize,
                         SMEM_BYTES);

    reset_kernel<<<1, 32>>>();
    convert_x<<<(NTOK * H / 4) / 256, 256>>>(x);
    convert_w<<<dim3(H / 32, H / 32, NEXP), 256>>>(W);
    router_kernel<<<128, 256>>>(x, rw);
    expert_gemm<<<dim3(MAXPE / BM, H / BN, NEXP), 256, SMEM_BYTES>>>();
    combine_kernel<<<(NTOK * H / 4) / 256, 256>>>(out);
}

// round 6
// speedup vs baseline: 2.4349x; 1.2345x over previous
#include <cuda_runtime.h>
#include <cuda_fp16.h>
#include <cstdint>

// TinyMoE: N=8192 tokens, H=1024, E=8, top-2.
// out[n,h] = sum_k w_k * (x[n] @ W_{e_k})[h] + C_n
//
// R6: fp16 HMMA GEMM (R5) + fused router/convert_x (single x pass),
// single-barrier pipeline mainloop, fp16 scatter buffers.

#define H      1024
#define NTOK   8192
#define NEXP   8
#define MAXPE  16384
#define BM     128
#define BN     128
#define BKH    64            // fp16 per k-slab (128 bytes)
#define KITER  (H / BKH)     // 16
#define PSTAGE 3

__device__ int    g_count[NEXP];
__device__ int    g_tok [NEXP][MAXPE];
__device__ float  g_wt  [NEXP][MAXPE];
__device__ int    g_slot[NEXP][MAXPE];
__device__ float  g_C   [NTOK];
__device__ __half g_buf [2][(size_t)NTOK * H];
__device__ __half g_xh[(size_t)NTOK * H];
__device__ __half g_wh[(size_t)NEXP * H * H];   // [e][out][in]

// ------------------------------------------------------------------ utils
__device__ __forceinline__ uint32_t smem_u32(const void* p) {
    uint32_t a;
    asm("{ .reg .u64 t; cvta.to.shared.u64 t, %1; cvt.u32.u64 %0, t; }"
        : "=r"(a) : "l"(p));
    return a;
}
#define SWZ(o) ((o) ^ ((((uint32_t)(o)) >> 3) & 0x70))

__device__ __forceinline__ void cp16(uint32_t d, const void* s) {
    asm volatile("cp.async.cg.shared.global [%0], [%1], 16;" :: "r"(d), "l"(s));
}
#define CP_COMMIT()  asm volatile("cp.async.commit_group;" ::: "memory")
#define CP_WAIT1()   asm volatile("cp.async.wait_group 1;" ::: "memory")

__device__ __forceinline__ void ldm4(uint32_t a, uint32_t& r0, uint32_t& r1,
                                     uint32_t& r2, uint32_t& r3) {
    asm volatile("ldmatrix.sync.aligned.m8n8.x4.shared.b16 {%0,%1,%2,%3}, [%4];"
                 : "=r"(r0), "=r"(r1), "=r"(r2), "=r"(r3) : "r"(a));
}
__device__ __forceinline__ void mma16816(float* c, const uint32_t* a,
                                         uint32_t b0, uint32_t b1) {
    asm volatile(
        "mma.sync.aligned.m16n8k16.row.col.f32.f16.f16.f32 "
        "{%0,%1,%2,%3}, {%4,%5,%6,%7}, {%8,%9}, {%0,%1,%2,%3};"
        : "+f"(c[0]), "+f"(c[1]), "+f"(c[2]), "+f"(c[3])
        : "r"(a[0]), "r"(a[1]), "r"(a[2]), "r"(a[3]), "r"(b0), "r"(b1));
}

// ------------------------------------------------------------------ stage 0
__global__ void reset_kernel() {
    if (threadIdx.x < NEXP) g_count[threadIdx.x] = 0;
}

// ------------------------------------------------------------------ fused router + convert_x
// grid 1024 x 256thr; one warp per token: load x row once, emit fp16 row,
// compute 8 router logits, softmax/top2, bucket.
__global__ __launch_bounds__(256) void router_convert(const float* __restrict__ x,
                                                      const float* __restrict__ rw) {
    __shared__ float s_rw[NEXP * H];
    int t = threadIdx.x;
    {
        const float4* rwg = (const float4*)rw;
        float4* s4 = (float4*)s_rw;
        #pragma unroll
        for (int i = 0; i < (NEXP * H / 4) / 256; i++)
            s4[t + i * 256] = rwg[t + i * 256];
    }
    __syncthreads();

    int wid = t >> 5, lane = t & 31;
    int n = blockIdx.x * 8 + wid;
    const float4* xr = (const float4*)(x + (size_t)n * H);
    __half2* xo = (__half2*)(g_xh + (size_t)n * H);
    const float4* rw4 = (const float4*)s_rw;

    float acc[NEXP];
    #pragma unroll
    for (int e = 0; e < NEXP; e++) acc[e] = 0.f;
    #pragma unroll
    for (int i = 0; i < 8; i++) {
        float4 xv = xr[i * 32 + lane];
        xo[(i * 32 + lane) * 2 + 0] = __floats2half2_rn(xv.x, xv.y);
        xo[(i * 32 + lane) * 2 + 1] = __floats2half2_rn(xv.z, xv.w);
        #pragma unroll
        for (int e = 0; e < NEXP; e++) {
            float4 rv = rw4[e * 256 + i * 32 + lane];
            acc[e] += xv.x * rv.x + xv.y * rv.y + xv.z * rv.z + xv.w * rv.w;
        }
    }
    #pragma unroll
    for (int e = 0; e < NEXP; e++) {
        #pragma unroll
        for (int off = 16; off > 0; off >>= 1)
            acc[e] += __shfl_xor_sync(0xffffffffu, acc[e], off);
    }
    if (lane == 0) {
        float m = acc[0];
        #pragma unroll
        for (int e = 1; e < NEXP; e++) m = fmaxf(m, acc[e]);
        float p[NEXP]; float s = 0.f;
        #pragma unroll
        for (int e = 0; e < NEXP; e++) { p[e] = expf(acc[e] - m); s += p[e]; }
        float inv = 1.f / s;
        int b1 = 0; float v1 = acc[0];
        #pragma unroll
        for (int e = 1; e < NEXP; e++) if (acc[e] > v1) { v1 = acc[e]; b1 = e; }
        int b2 = -1; float v2 = -3.4e38f;
        #pragma unroll
        for (int e = 0; e < NEXP; e++)
            if (e != b1 && acc[e] > v2) { v2 = acc[e]; b2 = e; }
        float p0 = p[b1] * inv, p1 = p[b2] * inv;
        float ws = 1.f / (p0 + p1 + 1e-6f);
        float w0 = p0 * ws, w1 = p1 * ws;
        g_C[n] = w0 * p0 + w1 * p1;
        int pos0 = atomicAdd(&g_count[b1], 1);
        g_tok[b1][pos0] = n; g_wt[b1][pos0] = w0; g_slot[b1][pos0] = 0;
        int pos1 = atomicAdd(&g_count[b2], 1);
        g_tok[b2][pos1] = n; g_wt[b2][pos1] = w1; g_slot[b2][pos1] = 1;
    }
}

// ------------------------------------------------------------------ convert+transpose W
__global__ __launch_bounds__(256) void convert_w(const float* __restrict__ W) {
    __shared__ float tile[32][33];
    int e = blockIdx.z, h0 = blockIdx.x * 32, o0 = blockIdx.y * 32;
    int tx = threadIdx.x & 31, ty = threadIdx.x >> 5;
    const float* src = W + ((size_t)e * H + h0) * H + o0;
    #pragma unroll
    for (int r = ty; r < 32; r += 8)
        tile[r][tx] = src[(size_t)r * H + tx];
    __syncthreads();
    #pragma unroll
    for (int r = ty; r < 32; r += 8) {
        float v = tile[tx][r];   // W[h0+tx][o0+r]
        g_wh[((size_t)e * H + o0 + r) * H + h0 + tx] = __float2half_rn(v);
    }
}

// ------------------------------------------------------------------ HMMA GEMM
#define STAGE_BYTES 32768                       // A 16KB + B 16KB
#define SMEM_BYTES  (PSTAGE * STAGE_BYTES)      // 96 KB -> 2 CTAs/SM

__global__ __launch_bounds__(256, 2) void expert_gemm() {
    extern __shared__ char smem[];
    __shared__ int   s_tok[BM];
    __shared__ float s_wt [BM];
    __shared__ int   s_slot[BM];

    int e = blockIdx.z;
    int cnt = g_count[e];
    int m0 = blockIdx.x * BM;
    if (m0 >= cnt) return;
    int n0 = blockIdx.y * BN;

    int t = threadIdx.x;
    if (t < BM) {
        int src = min(m0 + t, cnt - 1);
        s_tok[t]  = g_tok[e][src];
        s_wt[t]   = g_wt[e][src];
        s_slot[t] = g_slot[e][src];
    }
    __syncthreads();

    const uint32_t sb = smem_u32(smem);

    // ---- loader: thread t covers rows lr+32*i (i<4), 16B chunk lc
    const int lr = t >> 3, lc = t & 7;
    const __half* aptr[4];
    const __half* bptr[4];
    #pragma unroll
    for (int i = 0; i < 4; i++) {
        int r = lr + 32 * i;
        aptr[i] = g_xh + (size_t)s_tok[r] * H + lc * 8;
        bptr[i] = g_wh + ((size_t)e * H + n0 + r) * H + lc * 8;
    }
    const uint32_t dsw = SWZ(lr * 128 + lc * 16);

    #define ISSUE(it) do {                                                   \
        int _st = (it) % PSTAGE; int _k0 = (it) * BKH;                       \
        uint32_t _ab = sb + _st * STAGE_BYTES;                               \
        uint32_t _bb = _ab + 16384;                                          \
        _Pragma("unroll")                                                    \
        for (int _i = 0; _i < 4; _i++) {                                     \
            cp16(_ab + (dsw + _i * 4096), aptr[_i] + _k0);                   \
            cp16(_bb + (dsw + _i * 4096), bptr[_i] + _k0);                   \
        }                                                                    \
    } while (0)

    ISSUE(0); CP_COMMIT();
    ISSUE(1); CP_COMMIT();

    // ---- compute setup: 8 warps as 2(M) x 4(N), warp tile 64x32
    int lane = t & 31, wid = t >> 5;
    int wm = wid & 1, wn = wid >> 1;
    int arow0 = wm * 64 + (lane & 15);
    int brow0 = wn * 32 + (lane & 15);
    int csel  = (lane >> 4) * 16;

    float acc[4][4][4];
    #pragma unroll
    for (int a = 0; a < 4; a++)
        #pragma unroll
        for (int b = 0; b < 4; b++)
            #pragma unroll
            for (int c = 0; c < 4; c++) acc[a][b][c] = 0.f;

    for (int it = 0; it < KITER; it++) {
        CP_WAIT1();
        __syncthreads();           // single barrier per iteration
        if (it + 2 < KITER) { ISSUE(it + 2); }
        CP_COMMIT();

        uint32_t ab = sb + (it % PSTAGE) * STAGE_BYTES;
        uint32_t bb = ab + 16384;
        #pragma unroll
        for (int kk = 0; kk < 4; kk++) {
            int colb = kk * 32 + csel;
            uint32_t afr[4][4];
            #pragma unroll
            for (int im = 0; im < 4; im++)
                ldm4(ab + SWZ((arow0 + im * 16) * 128 + colb),
                     afr[im][0], afr[im][1], afr[im][2], afr[im][3]);
            uint32_t bfr[2][4];
            #pragma unroll
            for (int j = 0; j < 2; j++)
                ldm4(bb + SWZ((brow0 + j * 16) * 128 + colb),
                     bfr[j][0], bfr[j][1], bfr[j][2], bfr[j][3]);
            #pragma unroll
            for (int im = 0; im < 4; im++) {
                mma16816(acc[im][0], afr[im], bfr[0][0], bfr[0][2]);
                mma16816(acc[im][1], afr[im], bfr[0][1], bfr[0][3]);
                mma16816(acc[im][2], afr[im], bfr[1][0], bfr[1][2]);
                mma16816(acc[im][3], afr[im], bfr[1][1], bfr[1][3]);
            }
        }
        // no trailing barrier: next iter's post-WAIT sync protects stage reuse
    }

    // ---- epilogue: scale by routing weight, scatter fp16 rows
    int qr = lane >> 2, qc = (lane & 3) * 2;
    #pragma unroll
    for (int im = 0; im < 4; im++) {
        #pragma unroll
        for (int p = 0; p < 2; p++) {
            int r = wm * 64 + im * 16 + p * 8 + qr;
            if (m0 + r < cnt) {
                float wt = s_wt[r];
                __half* dst = g_buf[s_slot[r]] + (size_t)s_tok[r] * H + n0 + wn * 32 + qc;
                #pragma unroll
                for (int inn = 0; inn < 4; inn++) {
                    *(__half2*)(dst + inn * 8) =
                        __floats2half2_rn(acc[im][inn][p * 2 + 0] * wt,
                                          acc[im][inn][p * 2 + 1] * wt);
                }
            }
        }
    }
}

// ------------------------------------------------------------------ combine
__global__ __launch_bounds__(256) void combine_kernel(float* __restrict__ out) {
    size_t idx = (size_t)blockIdx.x * 256 + threadIdx.x;  // float4 / half4 index
    int n = (int)(idx >> 8);
    const __half2* a2 = (const __half2*)g_buf[0] + idx * 2;
    const __half2* b2 = (const __half2*)g_buf[1] + idx * 2;
    float2 a0 = __half22float2(a2[0]), a1 = __half22float2(a2[1]);
    float2 b0 = __half22float2(b2[0]), b1 = __half22float2(b2[1]);
    float  c = g_C[n];
    float4 o;
    o.x = a0.x + b0.x + c;
    o.y = a0.y + b0.y + c;
    o.z = a1.x + b1.x + c;
    o.w = a1.y + b1.y + c;
    ((float4*)out)[idx] = o;
}

// ------------------------------------------------------------------ launch
extern "C" void kernel_launch(void* const* d_in, const int* in_sizes, int n_in,
                              void* d_out, int out_size) {
    const float* x  = (const float*)d_in[0];   // [8192, 1024]
    const float* rw = (const float*)d_in[1];   // [8, 1024]
    const float* W  = (const float*)d_in[2];   // [8, 1024, 1024]
    float* out = (float*)d_out;

    cudaFuncSetAttribute(expert_gemm, cudaFuncAttributeMaxDynamicSharedMemorySize,
                         SMEM_BYTES);

    reset_kernel<<<1, 32>>>();
    router_convert<<<NTOK / 8, 256>>>(x, rw);
    convert_w<<<dim3(H / 32, H / 32, NEXP), 256>>>(W);
    expert_gemm<<<dim3(MAXPE / BM, H / BN, NEXP), 256, SMEM_BYTES>>>();
    combine_kernel<<<(NTOK * H / 4) / 256, 256>>>(out);
}